// round 5
// baseline (speedup 1.0000x reference)
#include <cuda_runtime.h>

#define N     2048
#define FIN   512
#define F     64

typedef unsigned long long u64;

// ---------------- scratch (static device allocations only) ----------------
__device__ float g_h[N * F];                 // 512 KB
__device__ float g_rowsum[N];
__device__ float g_opart[8][N * F];          // 4 MB: j-split partials of P@h

#define ABS2MASK 0x7FFFFFFF7FFFFFFFULL

__device__ __forceinline__ u64 f2add(u64 a, u64 b) {
    u64 r; asm("add.rn.f32x2 %0, %1, %2;" : "=l"(r) : "l"(a), "l"(b)); return r;
}
__device__ __forceinline__ u64 f2fma(u64 a, u64 b, u64 c) {
    u64 r; asm("fma.rn.f32x2 %0, %1, %2, %3;" : "=l"(r) : "l"(a), "l"(b), "l"(c)); return r;
}
__device__ __forceinline__ u64 dupf(float x) {
    u64 r; unsigned u = __float_as_uint(x);
    asm("mov.b64 %0, {%1,%1};" : "=l"(r) : "r"(u)); return r;
}
__device__ __forceinline__ float unpack_sum(u64 v) {
    float lo, hi;
    asm("mov.b64 {%0,%1}, %2;" : "=f"(lo), "=f"(hi) : "l"(v));
    return lo + hi;
}
__device__ __forceinline__ void unpack2(u64 v, float& lo, float& hi) {
    asm("mov.b64 {%0,%1}, %2;" : "=f"(lo), "=f"(hi) : "l"(v));
}

#define FMA4(a, s, v) { (a).x += (s)*(v).x; (a).y += (s)*(v).y; (a).z += (s)*(v).z; (a).w += (s)*(v).w; }

// ---------------- init ------------------------------------------------------
__global__ void init_rows() {
    int i = blockIdx.x * blockDim.x + threadIdx.x;
    if (i < N) g_rowsum[i] = 0.0f;
}

// ---------------- K1: h = x @ W  (N x FIN) @ (FIN x F) ---------------------
__global__ __launch_bounds__(256) void k1_gemm_h(const float* __restrict__ x,
                                                 const float* __restrict__ W) {
    __shared__ float xs[16][FIN];   // 32 KB
    __shared__ float ws[32][F];     // 8 KB
    int tid = threadIdx.x;
    int r0 = blockIdx.x * 16;

    const float4* xg  = (const float4*)(x + (size_t)r0 * FIN);
    float4*       xs4 = (float4*)&xs[0][0];
#pragma unroll
    for (int u = 0; u < 8; u++) xs4[tid + u * 256] = xg[tid + u * 256];

    int tx = tid & 15;
    int ty = tid >> 4;
    float4 acc[4];
#pragma unroll
    for (int q = 0; q < 4; q++) acc[q] = make_float4(0.f, 0.f, 0.f, 0.f);

    for (int kt = 0; kt < FIN; kt += 32) {
        __syncthreads();
        const float4* wg  = (const float4*)(W + (size_t)kt * F);
        float4*       ws4 = (float4*)&ws[0][0];
        ws4[tid]       = wg[tid];
        ws4[tid + 256] = wg[tid + 256];
        __syncthreads();
#pragma unroll
        for (int k4 = 0; k4 < 8; k4++) {
            float4 xv = *(const float4*)&xs[ty][kt + k4 * 4];
            float4 w0 = ((const float4*)&ws[k4 * 4 + 0][0])[tx];
            float4 w1 = ((const float4*)&ws[k4 * 4 + 1][0])[tx];
            float4 w2 = ((const float4*)&ws[k4 * 4 + 2][0])[tx];
            float4 w3 = ((const float4*)&ws[k4 * 4 + 3][0])[tx];
            FMA4(acc[0], xv.x, w0); FMA4(acc[1], xv.y, w1);
            FMA4(acc[2], xv.z, w2); FMA4(acc[3], xv.w, w3);
        }
    }
    float4 r;
    r.x = (acc[0].x + acc[1].x) + (acc[2].x + acc[3].x);
    r.y = (acc[0].y + acc[1].y) + (acc[2].y + acc[3].y);
    r.z = (acc[0].z + acc[1].z) + (acc[2].z + acc[3].z);
    r.w = (acc[0].w + acc[1].w) + (acc[2].w + acc[3].w);
    *(float4*)&g_h[(size_t)(r0 + ty) * F + tx * 4] = r;
}

// ---------------- K23: fused scores + exp + P@h (no S tensor, no rowmax) ---
// Block = i-tile 64 rows x j-chunk 256 (4 subtiles of 64). Grid (32, 8).
// exp without max-subtraction: scores = relu(...) in [0, ~20] -> fp32 safe.
// Phase A (per subtile): 64x64 score tile, k2 micro (rotated smem layout),
//   mask+exp in regs, local rowsum, P stored transposed+swizzled to Pst.
// Phase B: P@h micro; h read from the SAME negated staging njs (O = -sum).
#define K23_SMEM ((4096 * 3 + 64) * 4)

__global__ __launch_bounds__(256) void k23_fused(const int* __restrict__ adj,
                                                 const float* __restrict__ a) {
    extern __shared__ float sm[];
    float* his = sm;           // [64][64] rotated by row/4 (i-tile h)
    float* njs = sm + 4096;    // [64][64] rotated, negated (j-subtile h)
    float* Pst = sm + 8192;    // [64 j][64 i] xor-swizzled exp'd scores
    float* as_ = sm + 12288;   // [64]

    int tid = threadIdx.x;
    int tx = tid & 15, ty = tid >> 4;
    int ib = blockIdx.x, gy = blockIdx.y;
    int gi0 = ib * 64;

    // stage his once (rotated: logical chunk c of row r at (c + r/4) & 15)
    const float4* hgi = (const float4*)(g_h + (size_t)gi0 * F);
#pragma unroll
    for (int u = 0; u < 4; u++) {
        int v = tid + u * 256;
        int r = v >> 4, c = v & 15;
        int cp = (c + (r >> 2)) & 15;
        *(float4*)&his[r * 64 + cp * 4] = hgi[v];
    }
    if (tid < 16) ((float4*)as_)[tid] = ((const float4*)a)[tid];

    int i0 = ty * 4, j0 = tx * 4;
    u64 accB[4][2] = {};                 // [i][f-pair]; accumulates -O
    float rsum[4] = {0.f, 0.f, 0.f, 0.f};
    int swzA = (tx & 7) * 4;             // swizzle key for rows j0..j0+3

    for (int jt = 0; jt < 4; jt++) {
        int j0g = gy * 256 + jt * 64;

        // prefetch j-subtile h and adj into regs (hides L2/DRAM latency)
        float4 hreg[4];
        const float4* hgj = (const float4*)(g_h + (size_t)j0g * F);
#pragma unroll
        for (int u = 0; u < 4; u++) hreg[u] = hgj[tid + u * 256];
        int4 adreg[4];
#pragma unroll
        for (int k = 0; k < 4; k++)
            adreg[k] = *(const int4*)&adj[(size_t)(gi0 + i0 + k) * N + j0g + j0];

        __syncthreads();   // prev phase B done with njs/Pst (1st iter: his/as_ ready)

        // stage njs: negated + rotated
#pragma unroll
        for (int u = 0; u < 4; u++) {
            int v = tid + u * 256;
            int r = v >> 4, c = v & 15;
            int cp = (c + (r >> 2)) & 15;
            float4 nv = hreg[u];
            nv.x = -nv.x; nv.y = -nv.y; nv.z = -nv.z; nv.w = -nv.w;
            *(float4*)&njs[r * 64 + cp * 4] = nv;
        }
        __syncthreads();

        // ---- phase A: 64x64 scores, thread = 4i x 4j ----
        u64 accA[4][4] = {};
#pragma unroll
        for (int fc = 0; fc < 16; fc++) {
            ulonglong2 av = *(const ulonglong2*)&as_[fc * 4];
            int ci = ((fc + ty) & 15) * 4;
            int cj = ((fc + tx) & 15) * 4;
            ulonglong2 hr[4], nj[4];
#pragma unroll
            for (int k = 0; k < 4; k++) {
                hr[k] = *(const ulonglong2*)&his[(i0 + k) * 64 + ci];
                nj[k] = *(const ulonglong2*)&njs[(j0 + k) * 64 + cj];
            }
#pragma unroll
            for (int k = 0; k < 4; k++) {
#pragma unroll
                for (int jj = 0; jj < 4; jj++) {
                    u64 d0 = f2add(hr[k].x, nj[jj].x) & ABS2MASK;
                    accA[k][jj] = f2fma(d0, av.x, accA[k][jj]);
                    u64 d1 = f2add(hr[k].y, nj[jj].y) & ABS2MASK;
                    accA[k][jj] = f2fma(d1, av.y, accA[k][jj]);
                }
            }
        }

        // mask + exp (no max subtraction), rowsum, store P transposed
#pragma unroll
        for (int k = 0; k < 4; k++) {
            float4 e;
            e.x = (adreg[k].x > 0) ? __expf(fmaxf(unpack_sum(accA[k][0]), 0.f)) : 0.f;
            e.y = (adreg[k].y > 0) ? __expf(fmaxf(unpack_sum(accA[k][1]), 0.f)) : 0.f;
            e.z = (adreg[k].z > 0) ? __expf(fmaxf(unpack_sum(accA[k][2]), 0.f)) : 0.f;
            e.w = (adreg[k].w > 0) ? __expf(fmaxf(unpack_sum(accA[k][3]), 0.f)) : 0.f;
            rsum[k] += (e.x + e.y) + (e.z + e.w);
            int col = (i0 + k) ^ swzA;
            Pst[(j0 + 0) * 64 + col] = e.x;
            Pst[(j0 + 1) * 64 + col] = e.y;
            Pst[(j0 + 2) * 64 + col] = e.z;
            Pst[(j0 + 3) * 64 + col] = e.w;
        }
        __syncthreads();

        // ---- phase B: accB += P[jq][i0..i0+3] * (-h[jq][4tx..4tx+3]) ----
#pragma unroll 4
        for (int jq = 0; jq < 64; jq++) {
            int swz = ((jq >> 2) & 7) * 4;
            float4 p = *(const float4*)&Pst[jq * 64 + (i0 ^ swz)];
            int cf = (((jq >> 2) + tx) & 15) * 4;
            ulonglong2 hv = *(const ulonglong2*)&njs[jq * 64 + cf];
            u64 p0 = dupf(p.x), p1 = dupf(p.y), p2 = dupf(p.z), p3 = dupf(p.w);
            accB[0][0] = f2fma(p0, hv.x, accB[0][0]);
            accB[0][1] = f2fma(p0, hv.y, accB[0][1]);
            accB[1][0] = f2fma(p1, hv.x, accB[1][0]);
            accB[1][1] = f2fma(p1, hv.y, accB[1][1]);
            accB[2][0] = f2fma(p2, hv.x, accB[2][0]);
            accB[2][1] = f2fma(p2, hv.y, accB[2][1]);
            accB[3][0] = f2fma(p3, hv.x, accB[3][0]);
            accB[3][1] = f2fma(p3, hv.y, accB[3][1]);
        }
    }

    // ---- rowsum: reduce over 16 tx lanes, one atomic per row ----
#pragma unroll
    for (int o = 8; o >= 1; o >>= 1) {
#pragma unroll
        for (int k = 0; k < 4; k++)
            rsum[k] += __shfl_xor_sync(0xffffffffu, rsum[k], o);
    }
    if (tx == 0) {
#pragma unroll
        for (int k = 0; k < 4; k++)
            atomicAdd(&g_rowsum[gi0 + i0 + k], rsum[k]);
    }

    // ---- epilogue: O = -accB ----
#pragma unroll
    for (int k = 0; k < 4; k++) {
        float a0, a1, a2, a3;
        unpack2(accB[k][0], a0, a1);
        unpack2(accB[k][1], a2, a3);
        *(float4*)&g_opart[gy][(size_t)(gi0 + i0 + k) * F + tx * 4] =
            make_float4(-a0, -a1, -a2, -a3);
    }
}

// ---------------- K4: out = relu((sum of 8 partials) / rowsum) -------------
__global__ __launch_bounds__(256) void k4_final(float* __restrict__ out) {
    int idx = blockIdx.x * blockDim.x + threadIdx.x;   // over N*F/4 float4s
    int i = idx >> 4;
    float inv = 1.0f / g_rowsum[i];
    float4 s = make_float4(0.f, 0.f, 0.f, 0.f);
#pragma unroll
    for (int p = 0; p < 8; p++) {
        float4 v = ((const float4*)g_opart[p])[idx];
        s.x += v.x; s.y += v.y; s.z += v.z; s.w += v.w;
    }
    float4 r;
    r.x = fmaxf(s.x * inv, 0.f);
    r.y = fmaxf(s.y * inv, 0.f);
    r.z = fmaxf(s.z * inv, 0.f);
    r.w = fmaxf(s.w * inv, 0.f);
    ((float4*)out)[idx] = r;
}

// ---------------- launch ---------------------------------------------------
extern "C" void kernel_launch(void* const* d_in, const int* in_sizes, int n_in,
                              void* d_out, int out_size) {
    const float* x   = (const float*)d_in[0];
    const int*   adj = (const int*)  d_in[1];
    const float* W   = (const float*)d_in[2];
    const float* a   = (const float*)d_in[3];
    float*       out = (float*)d_out;

    cudaFuncSetAttribute(k23_fused, cudaFuncAttributeMaxDynamicSharedMemorySize, K23_SMEM);

    init_rows<<<8, 256>>>();
    k1_gemm_h<<<128, 256>>>(x, W);
    dim3 g23(32, 8);
    k23_fused<<<g23, 256, K23_SMEM>>>(adj, a);
    k4_final<<<128, 256>>>(out);
}

// round 7
// speedup vs baseline: 1.1453x; 1.1453x over previous
#include <cuda_runtime.h>

#define N     2048
#define FIN   512
#define F     64
#define NT    32            // 64-row tiles per dimension
#define NTRI  528           // NT*(NT+1)/2

typedef unsigned long long u64;

// ---------------- scratch (static device allocations only) ----------------
__device__ float g_h[N * F];                 // 512 KB
__device__ float g_rowsum[N];
__device__ float g_opart[NT][N * F];         // 16 MB: slot = other tile index

#define ABS2MASK 0x7FFFFFFF7FFFFFFFULL

__device__ __forceinline__ u64 f2add(u64 a, u64 b) {
    u64 r; asm("add.rn.f32x2 %0, %1, %2;" : "=l"(r) : "l"(a), "l"(b)); return r;
}
__device__ __forceinline__ u64 f2fma(u64 a, u64 b, u64 c) {
    u64 r; asm("fma.rn.f32x2 %0, %1, %2, %3;" : "=l"(r) : "l"(a), "l"(b), "l"(c)); return r;
}
__device__ __forceinline__ u64 dupf(float x) {
    u64 r; unsigned u = __float_as_uint(x);
    asm("mov.b64 %0, {%1,%1};" : "=l"(r) : "r"(u)); return r;
}
__device__ __forceinline__ float unpack_sum(u64 v) {
    float lo, hi;
    asm("mov.b64 {%0,%1}, %2;" : "=f"(lo), "=f"(hi) : "l"(v));
    return lo + hi;
}
__device__ __forceinline__ void unpack2(u64 v, float& lo, float& hi) {
    asm("mov.b64 {%0,%1}, %2;" : "=f"(lo), "=f"(hi) : "l"(v));
}

#define FMA4(a, s, v) { (a).x += (s)*(v).x; (a).y += (s)*(v).y; (a).z += (s)*(v).z; (a).w += (s)*(v).w; }

// ---------------- init ------------------------------------------------------
__global__ void init_rows() {
    int i = blockIdx.x * blockDim.x + threadIdx.x;
    if (i < N) g_rowsum[i] = 0.0f;
}

// ---------------- K1: h = x @ W  (N x FIN) @ (FIN x F) ---------------------
__global__ __launch_bounds__(256) void k1_gemm_h(const float* __restrict__ x,
                                                 const float* __restrict__ W) {
    __shared__ float xs[16][FIN];   // 32 KB
    __shared__ float ws[32][F];     // 8 KB
    int tid = threadIdx.x;
    int r0 = blockIdx.x * 16;

    const float4* xg  = (const float4*)(x + (size_t)r0 * FIN);
    float4*       xs4 = (float4*)&xs[0][0];
#pragma unroll
    for (int u = 0; u < 8; u++) xs4[tid + u * 256] = xg[tid + u * 256];

    int tx = tid & 15;
    int ty = tid >> 4;
    float4 acc[4];
#pragma unroll
    for (int q = 0; q < 4; q++) acc[q] = make_float4(0.f, 0.f, 0.f, 0.f);

    for (int kt = 0; kt < FIN; kt += 32) {
        __syncthreads();
        const float4* wg  = (const float4*)(W + (size_t)kt * F);
        float4*       ws4 = (float4*)&ws[0][0];
        ws4[tid]       = wg[tid];
        ws4[tid + 256] = wg[tid + 256];
        __syncthreads();
#pragma unroll
        for (int k4 = 0; k4 < 8; k4++) {
            float4 xv = *(const float4*)&xs[ty][kt + k4 * 4];
            float4 w0 = ((const float4*)&ws[k4 * 4 + 0][0])[tx];
            float4 w1 = ((const float4*)&ws[k4 * 4 + 1][0])[tx];
            float4 w2 = ((const float4*)&ws[k4 * 4 + 2][0])[tx];
            float4 w3 = ((const float4*)&ws[k4 * 4 + 3][0])[tx];
            FMA4(acc[0], xv.x, w0); FMA4(acc[1], xv.y, w1);
            FMA4(acc[2], xv.z, w2); FMA4(acc[3], xv.w, w3);
        }
    }
    float4 r;
    r.x = (acc[0].x + acc[1].x) + (acc[2].x + acc[3].x);
    r.y = (acc[0].y + acc[1].y) + (acc[2].y + acc[3].y);
    r.z = (acc[0].z + acc[1].z) + (acc[2].z + acc[3].z);
    r.w = (acc[0].w + acc[1].w) + (acc[2].w + acc[3].w);
    *(float4*)&g_h[(size_t)(r0 + ty) * F + tx * 4] = r;
}

// ---------------- K23sym: symmetric fused scores + exp + both AV products --
// One block per upper-triangle tile pair (ib <= jb).
// e[i,j] symmetric; exp computed once, masked twice (adj not symmetric).
// Phase A: 64x64 E tile (4i x 4j/thread, rotated smem layout).
// Phase B1: O_i += P_ij @ h_j  (Pst1[j][i], njs negated -> negate at end).
// Phase B2: O_j += P_ji^T @ h_i (Pst2[i][j], his) -- off-diagonal only.
// NOTE: in phase B all 16 tx lanes load IDENTICAL p values, so each lane's
// rsum is already the full tile-row sum -> atomicAdd from tx==0 directly,
// NO cross-lane reduction (R6 bug: reducing multiplied rowsum by 16).
#define K23S_SMEM ((4096 * 4 + 64) * 4)   // his, njs, Pst1, Pst2, a = 64.3KB

__global__ __launch_bounds__(256, 2) void k23_sym(const int* __restrict__ adj,
                                                  const float* __restrict__ a) {
    extern __shared__ float sm[];
    float* his  = sm;            // [64][64] rotated (i-tile h)
    float* njs  = sm + 4096;     // [64][64] rotated, negated (j-tile h)
    float* Pst1 = sm + 8192;     // [j][i] swizzled, mask adj[i,j]
    float* Pst2 = sm + 12288;    // [i][j] swizzled, mask adj[j,i]
    float* as_  = sm + 16384;    // [64]

    // triangular decode
    int t = blockIdx.x, ib = 0;
    while (t >= NT - ib) { t -= NT - ib; ib++; }
    int jb = ib + t;
    int gi0 = ib * 64, gj0 = jb * 64;
    bool diag = (ib == jb);

    int tid = threadIdx.x;
    int tx = tid & 15, ty = tid >> 4;
    int i0 = ty * 4, j0 = tx * 4;

    // ---- prefetch adjacency (both orientations), compress to bitmasks ----
    unsigned mij = 0, mji = 0;
#pragma unroll
    for (int k = 0; k < 4; k++) {
        int4 v = *(const int4*)&adj[(size_t)(gi0 + i0 + k) * N + gj0 + j0];
        unsigned b = (v.x > 0) | ((v.y > 0) << 1) | ((v.z > 0) << 2) | ((v.w > 0) << 3);
        mij |= b << (k * 4);     // bit (k*4+jj) = adj[gi0+i0+k][gj0+j0+jj]
    }
    if (!diag) {
#pragma unroll
        for (int jj = 0; jj < 4; jj++) {
            int4 v = *(const int4*)&adj[(size_t)(gj0 + j0 + jj) * N + gi0 + i0];
            unsigned b = (v.x > 0) | ((v.y > 0) << 1) | ((v.z > 0) << 2) | ((v.w > 0) << 3);
            mji |= b << (jj * 4);  // bit (jj*4+k) = adj[gj0+j0+jj][gi0+i0+k]
        }
    }

    // ---- stage his (rotated), njs (rotated + negated), a ----
    const float4* hgi = (const float4*)(g_h + (size_t)gi0 * F);
    const float4* hgj = (const float4*)(g_h + (size_t)gj0 * F);
#pragma unroll
    for (int u = 0; u < 4; u++) {
        int v = tid + u * 256;
        int r = v >> 4, c = v & 15;
        int cp = (c + (r >> 2)) & 15;
        *(float4*)&his[r * 64 + cp * 4] = hgi[v];
        float4 nv = hgj[v];
        nv.x = -nv.x; nv.y = -nv.y; nv.z = -nv.z; nv.w = -nv.w;
        *(float4*)&njs[r * 64 + cp * 4] = nv;
    }
    if (tid < 16) ((float4*)as_)[tid] = ((const float4*)a)[tid];
    __syncthreads();

    // ---- phase A: E tile, thread = 4i x 4j ----
    u64 accA[4][4] = {};
#pragma unroll
    for (int fc = 0; fc < 16; fc++) {
        ulonglong2 av = *(const ulonglong2*)&as_[fc * 4];
        int ci = ((fc + ty) & 15) * 4;
        int cj = ((fc + tx) & 15) * 4;
        ulonglong2 hr[4], nj[4];
#pragma unroll
        for (int k = 0; k < 4; k++) {
            hr[k] = *(const ulonglong2*)&his[(i0 + k) * 64 + ci];
            nj[k] = *(const ulonglong2*)&njs[(j0 + k) * 64 + cj];
        }
#pragma unroll
        for (int k = 0; k < 4; k++) {
#pragma unroll
            for (int jj = 0; jj < 4; jj++) {
                u64 d0 = f2add(hr[k].x, nj[jj].x) & ABS2MASK;
                accA[k][jj] = f2fma(d0, av.x, accA[k][jj]);
                u64 d1 = f2add(hr[k].y, nj[jj].y) & ABS2MASK;
                accA[k][jj] = f2fma(d1, av.y, accA[k][jj]);
            }
        }
    }

    // ---- exp once, mask twice, store Pst1 / Pst2 ----
    int swzA = (tx & 7) * 4;    // key for rows j0..j0+3  ((j>>2)&7 == tx&7)
    int swzB = (ty & 7) * 4;    // key for rows i0..i0+3
#pragma unroll
    for (int k = 0; k < 4; k++) {
        float e[4];
#pragma unroll
        for (int jj = 0; jj < 4; jj++)
            e[jj] = __expf(fmaxf(unpack_sum(accA[k][jj]), 0.f));
        int col = (i0 + k) ^ swzA;
        Pst1[(j0 + 0) * 64 + col] = (mij >> (k * 4 + 0)) & 1 ? e[0] : 0.f;
        Pst1[(j0 + 1) * 64 + col] = (mij >> (k * 4 + 1)) & 1 ? e[1] : 0.f;
        Pst1[(j0 + 2) * 64 + col] = (mij >> (k * 4 + 2)) & 1 ? e[2] : 0.f;
        Pst1[(j0 + 3) * 64 + col] = (mij >> (k * 4 + 3)) & 1 ? e[3] : 0.f;
        if (!diag) {
            float4 st;
            st.x = (mji >> (0 * 4 + k)) & 1 ? e[0] : 0.f;
            st.y = (mji >> (1 * 4 + k)) & 1 ? e[1] : 0.f;
            st.z = (mji >> (2 * 4 + k)) & 1 ? e[2] : 0.f;
            st.w = (mji >> (3 * 4 + k)) & 1 ? e[3] : 0.f;
            *(float4*)&Pst2[(i0 + k) * 64 + (j0 ^ swzB)] = st;
        }
    }
    __syncthreads();

    // ---- phase B1: accBi = sum_j P_ij * (-h_j)  -> O_i = -accBi ----
    {
        u64 accB[4][2] = {};
        float rsum[4] = {0.f, 0.f, 0.f, 0.f};
#pragma unroll 4
        for (int jq = 0; jq < 64; jq++) {
            int swz = ((jq >> 2) & 7) * 4;
            float4 p = *(const float4*)&Pst1[jq * 64 + (i0 ^ swz)];
            int cf = (((jq >> 2) + tx) & 15) * 4;
            ulonglong2 hv = *(const ulonglong2*)&njs[jq * 64 + cf];
            rsum[0] += p.x; rsum[1] += p.y; rsum[2] += p.z; rsum[3] += p.w;
            u64 p0 = dupf(p.x), p1 = dupf(p.y), p2 = dupf(p.z), p3 = dupf(p.w);
            accB[0][0] = f2fma(p0, hv.x, accB[0][0]);
            accB[0][1] = f2fma(p0, hv.y, accB[0][1]);
            accB[1][0] = f2fma(p1, hv.x, accB[1][0]);
            accB[1][1] = f2fma(p1, hv.y, accB[1][1]);
            accB[2][0] = f2fma(p2, hv.x, accB[2][0]);
            accB[2][1] = f2fma(p2, hv.y, accB[2][1]);
            accB[3][0] = f2fma(p3, hv.x, accB[3][0]);
            accB[3][1] = f2fma(p3, hv.y, accB[3][1]);
        }
        // all tx lanes hold identical rsum (same Pst1 reads) -> no reduction
        if (tx == 0)
#pragma unroll
            for (int k = 0; k < 4; k++)
                atomicAdd(&g_rowsum[gi0 + i0 + k], rsum[k]);
#pragma unroll
        for (int k = 0; k < 4; k++) {
            float a0, a1, a2, a3;
            unpack2(accB[k][0], a0, a1);
            unpack2(accB[k][1], a2, a3);
            *(float4*)&g_opart[jb][(size_t)(gi0 + i0 + k) * F + tx * 4] =
                make_float4(-a0, -a1, -a2, -a3);
        }
    }

    // ---- phase B2: accBj = sum_i P_ji * h_i  -> O_j ----
    if (!diag) {
        u64 accB[4][2] = {};
        float rsum[4] = {0.f, 0.f, 0.f, 0.f};
#pragma unroll 4
        for (int iq = 0; iq < 64; iq++) {
            int swz = ((iq >> 2) & 7) * 4;
            float4 p = *(const float4*)&Pst2[iq * 64 + (i0 ^ swz)];  // j-rows i0.. of jb block
            int cf = (((iq >> 2) + tx) & 15) * 4;
            ulonglong2 hv = *(const ulonglong2*)&his[iq * 64 + cf];
            rsum[0] += p.x; rsum[1] += p.y; rsum[2] += p.z; rsum[3] += p.w;
            u64 p0 = dupf(p.x), p1 = dupf(p.y), p2 = dupf(p.z), p3 = dupf(p.w);
            accB[0][0] = f2fma(p0, hv.x, accB[0][0]);
            accB[0][1] = f2fma(p0, hv.y, accB[0][1]);
            accB[1][0] = f2fma(p1, hv.x, accB[1][0]);
            accB[1][1] = f2fma(p1, hv.y, accB[1][1]);
            accB[2][0] = f2fma(p2, hv.x, accB[2][0]);
            accB[2][1] = f2fma(p2, hv.y, accB[2][1]);
            accB[3][0] = f2fma(p3, hv.x, accB[3][0]);
            accB[3][1] = f2fma(p3, hv.y, accB[3][1]);
        }
        // identical rsum across tx lanes -> no reduction
        if (tx == 0)
#pragma unroll
            for (int k = 0; k < 4; k++)
                atomicAdd(&g_rowsum[gj0 + i0 + k], rsum[k]);
#pragma unroll
        for (int k = 0; k < 4; k++) {
            float a0, a1, a2, a3;
            unpack2(accB[k][0], a0, a1);
            unpack2(accB[k][1], a2, a3);
            *(float4*)&g_opart[ib][(size_t)(gj0 + i0 + k) * F + tx * 4] =
                make_float4(a0, a1, a2, a3);
        }
    }
}

// ---------------- K4: out = relu((sum of 32 partials) / rowsum) ------------
__global__ __launch_bounds__(256) void k4_final(float* __restrict__ out) {
    int idx = blockIdx.x * 256 + threadIdx.x;          // 0 .. N*F-1
    float inv = 1.0f / g_rowsum[idx >> 6];
    float s = 0.f;
#pragma unroll
    for (int p = 0; p < NT; p++) s += g_opart[p][idx];
    out[idx] = fmaxf(s * inv, 0.f);
}

// ---------------- launch ---------------------------------------------------
extern "C" void kernel_launch(void* const* d_in, const int* in_sizes, int n_in,
                              void* d_out, int out_size) {
    const float* x   = (const float*)d_in[0];
    const int*   adj = (const int*)  d_in[1];
    const float* W   = (const float*)d_in[2];
    const float* a   = (const float*)d_in[3];
    float*       out = (float*)d_out;

    cudaFuncSetAttribute(k23_sym, cudaFuncAttributeMaxDynamicSharedMemorySize, K23S_SMEM);

    init_rows<<<8, 256>>>();
    k1_gemm_h<<<128, 256>>>(x, W);
    k23_sym<<<NTRI, 256, K23S_SMEM>>>(adj, a);
    k4_final<<<N * F / 256, 256>>>(out);
}